// round 11
// baseline (speedup 1.0000x reference)
#include <cuda_runtime.h>
#include <math.h>
#include <stdint.h>

// Problem constants
#define SEQ     8192
#define BATCH   2
#define MTOT    (BATCH * SEQ)   // 16384
#define HIDDEN  768
#define KV      256
#define DMAX    7
#define NSM     148

// Scratch (static __device__ — no runtime allocation allowed)
__device__ float g_e[DMAX + 1];
__device__ __align__(16) float g_v[MTOT * KV];
__device__ __align__(16) float g_a[MTOT * KV];
__device__ __align__(16) float g_wv[KV * HIDDEN];   // tf32-pre-rounded Wv
__device__ __align__(16) float g_wo[HIDDEN * KV];   // tf32-pre-rounded Wo

// ---------------------------------------------------------------------------
// helpers
// ---------------------------------------------------------------------------
__device__ __forceinline__ uint32_t smem_u32(const void* p) {
    uint32_t a;
    asm("{ .reg .u64 t; cvta.to.shared.u64 t, %1; cvt.u32.u64 %0, t; }"
        : "=r"(a) : "l"(p));
    return a;
}

__device__ __forceinline__ uint32_t to_tf32_u(uint32_t x) {
    uint32_t u;
    asm("cvt.rna.tf32.f32 %0, %1;" : "=r"(u) : "f"(__uint_as_float(x)));
    return u;
}
__device__ __forceinline__ float to_tf32_f(float x) {
    uint32_t u;
    asm("cvt.rna.tf32.f32 %0, %1;" : "=r"(u) : "f"(x));
    return __uint_as_float(u);
}

__device__ __forceinline__ void ldsm4(uint32_t* r, uint32_t addr) {
    asm volatile("ldmatrix.sync.aligned.m8n8.x4.shared.b16 {%0,%1,%2,%3}, [%4];"
        : "=r"(r[0]), "=r"(r[1]), "=r"(r[2]), "=r"(r[3]) : "r"(addr));
}

__device__ __forceinline__ void mma_tf32(float* d, const uint32_t* a,
                                         const uint32_t* b) {
    asm volatile(
        "mma.sync.aligned.m16n8k8.row.col.f32.tf32.tf32.f32 "
        "{%0,%1,%2,%3}, {%4,%5,%6,%7}, {%8,%9}, {%0,%1,%2,%3};"
        : "+f"(d[0]), "+f"(d[1]), "+f"(d[2]), "+f"(d[3])
        : "r"(a[0]), "r"(a[1]), "r"(a[2]), "r"(a[3]), "r"(b[0]), "r"(b[1]));
}

#define CP_ASYNC16(dst, src) \
    asm volatile("cp.async.cg.shared.global [%0], [%1], 16;" \
                 :: "r"(dst), "l"(src) : "memory")
#define CP_COMMIT() asm volatile("cp.async.commit_group;" ::: "memory")
#define CP_WAIT2()  asm volatile("cp.async.wait_group 2;" ::: "memory")
#define CP_WAIT0()  asm volatile("cp.async.wait_group 0;" ::: "memory")

// SMEM geometry: rows padded to 36 floats (144B) -> conflict-free ldmatrix
#define ROWF    36
#define ASZ     (256 * ROWF * 4)           // A tile bytes: 36864
#define BSZ     (128 * ROWF * 4)           // B tile bytes: 18432
#define STGB    (ASZ + BSZ)                // 55296 per stage
#define NSTAGE  4                          // 4 stages = 216 KB

// ---------------------------------------------------------------------------
// Persistent-CTA single-pass TF32 GEMM (NT): C[m,n] = sum_k A[m*K+k]*B[n*K+k]
// fp32 in/out, tf32 mma. CVT_A: round A fragments (cvt.rna idempotent ->
// skipping on pre-rounded data is bit-identical).
// CTA tile 256x128, 512 threads (16 warps 4x4), warp tile 64x32, m16n8k8.
// 4-stage cp.async pipeline, one __syncthreads per chunk, fragment
// double-buffering. Grid = min(tiles, NSM); each CTA loops over tiles
// (stride gridDim.x) -> no wave quantization. NC must be ≡ 0 mod NSTAGE
// (next tile's prologue writes stages 0..2 while laggards read stage 3).
// ---------------------------------------------------------------------------
template <bool CVT_A>
__global__ __launch_bounds__(512, 1) void gemm_tf32(
    const float* __restrict__ A, const float* __restrict__ B,
    float* __restrict__ C, int M, int N, int K)
{
    extern __shared__ char dynsmem[];
    const uint32_t sb = (smem_u32(dynsmem) + 127u) & ~127u;

    const int tid  = threadIdx.x;
    const int wid  = tid >> 5;
    const int lane = tid & 31;
    const int NC   = K >> 5;
    const int nTilesN = N >> 7;                 // 128-wide n tiles
    const int nTiles  = (M >> 8) * nTilesN;     // 256-tall m tiles

    const int warpM = (wid >> 2) * 64;
    const int warpN = (wid & 3) * 32;

    // cp.async mapping (tile-relative)
    const int ra = tid >> 1;
    const int ha = tid & 1;
    const uint32_t sOffA = (uint32_t)(ra * ROWF + ha * 16) * 4u;
    const int rb = tid >> 2;
    const int hb = tid & 3;
    const uint32_t sOffB = (uint32_t)(rb * ROWF + hb * 8) * 4u;

    // ldmatrix lane->address components
    const uint32_t aOffF = (uint32_t)((warpM + (lane & 7) + 8 * ((lane >> 3) & 1))
                                      * ROWF + 4 * (lane >> 4));
    const uint32_t bOffF = (uint32_t)((warpN + ((lane >> 4) << 3) + (lane & 7))
                                      * ROWF + 4 * ((lane >> 3) & 1));

#define ISSUE_STAGE(stg, kt)                                              \
    do {                                                                  \
        uint32_t dA = sb + (uint32_t)(stg) * STGB + sOffA;                \
        uint32_t dB = sb + (uint32_t)(stg) * STGB + ASZ + sOffB;          \
        const float* pa = gA + (kt);                                      \
        const float* pb = gB + (kt);                                      \
        CP_ASYNC16(dA,      pa);                                          \
        CP_ASYNC16(dA + 16, pa + 4);                                      \
        CP_ASYNC16(dA + 32, pa + 8);                                      \
        CP_ASYNC16(dA + 48, pa + 12);                                     \
        CP_ASYNC16(dB,      pb);                                          \
        CP_ASYNC16(dB + 16, pb + 4);                                      \
        CP_COMMIT();                                                      \
    } while (0)

    for (int t = blockIdx.x; t < nTiles; t += gridDim.x) {
        const int bm = (t / nTilesN) * 256;
        const int bn = (t - (t / nTilesN) * nTilesN) * 128;

        const float* gA = A + (size_t)(bm + ra) * K + ha * 16;
        const float* gB = B + (size_t)(bn + rb) * K + hb * 8;

        float acc[4][4][4];
#pragma unroll
        for (int i = 0; i < 4; ++i)
#pragma unroll
            for (int j = 0; j < 4; ++j)
#pragma unroll
                for (int q = 0; q < 4; ++q) acc[i][j][q] = 0.f;

        // prologue: stages 0..2 in flight
        ISSUE_STAGE(0, 0);
        ISSUE_STAGE(1, 32);
        ISSUE_STAGE(2, 64);

        int stage = 0;
        for (int c = 0; c < NC; ++c) {
            CP_WAIT2();
            __syncthreads();

            if (c + 3 < NC) {
                int ns = stage + 3; if (ns >= NSTAGE) ns -= NSTAGE;
                ISSUE_STAGE(ns, (c + 3) * 32);
            }

            const uint32_t sA = sb + (uint32_t)stage * STGB + aOffF * 4u;
            const uint32_t sB = sb + (uint32_t)stage * STGB + ASZ + bOffF * 4u;

            if (CVT_A) {
                uint32_t bfr[2][2][4];
                ldsm4(bfr[0][0], sB);
                ldsm4(bfr[0][1], sB + 16u * ROWF * 4u);
#pragma unroll
                for (int ks = 0; ks < 4; ++ks) {
                    const int cur = ks & 1;
                    const uint32_t kb = (uint32_t)(ks * 8) * 4u;
                    uint32_t af[4][4];
#pragma unroll
                    for (int mt = 0; mt < 4; ++mt)
                        ldsm4(af[mt], sA + kb + (uint32_t)(mt * 16 * ROWF) * 4u);
                    if (ks < 3) {
                        const uint32_t kn = (uint32_t)((ks + 1) * 8) * 4u;
                        ldsm4(bfr[cur ^ 1][0], sB + kn);
                        ldsm4(bfr[cur ^ 1][1], sB + kn + 16u * ROWF * 4u);
                    }
#pragma unroll
                    for (int mt = 0; mt < 4; ++mt) {
#pragma unroll
                        for (int q = 0; q < 4; ++q)
                            af[mt][q] = to_tf32_u(af[mt][q]);
#pragma unroll
                        for (int nt = 0; nt < 4; ++nt)
                            mma_tf32(acc[mt][nt], af[mt],
                                     &bfr[cur][nt >> 1][(nt & 1) * 2]);
                    }
                }
            } else {
                uint32_t af[2][4][4], bfr[2][2][4];
#pragma unroll
                for (int mt = 0; mt < 4; ++mt)
                    ldsm4(af[0][mt], sA + (uint32_t)(mt * 16 * ROWF) * 4u);
                ldsm4(bfr[0][0], sB);
                ldsm4(bfr[0][1], sB + 16u * ROWF * 4u);
#pragma unroll
                for (int ks = 0; ks < 4; ++ks) {
                    const int cur = ks & 1;
                    if (ks < 3) {
                        const uint32_t kn = (uint32_t)((ks + 1) * 8) * 4u;
#pragma unroll
                        for (int mt = 0; mt < 4; ++mt)
                            ldsm4(af[cur ^ 1][mt],
                                  sA + kn + (uint32_t)(mt * 16 * ROWF) * 4u);
                        ldsm4(bfr[cur ^ 1][0], sB + kn);
                        ldsm4(bfr[cur ^ 1][1], sB + kn + 16u * ROWF * 4u);
                    }
#pragma unroll
                    for (int mt = 0; mt < 4; ++mt)
#pragma unroll
                        for (int nt = 0; nt < 4; ++nt)
                            mma_tf32(acc[mt][nt], af[cur][mt],
                                     &bfr[cur][nt >> 1][(nt & 1) * 2]);
                }
            }

            if (++stage >= NSTAGE) stage = 0;
        }
        CP_WAIT0();

        // epilogue: direct global stores
#pragma unroll
        for (int mt = 0; mt < 4; ++mt) {
#pragma unroll
            for (int nt = 0; nt < 4; ++nt) {
                int row = bm + warpM + mt * 16 + (lane >> 2);
                int col = bn + warpN + nt * 8 + (lane & 3) * 2;
                float2 v0 = make_float2(acc[mt][nt][0], acc[mt][nt][1]);
                float2 v1 = make_float2(acc[mt][nt][2], acc[mt][nt][3]);
                *reinterpret_cast<float2*>(C + (size_t)row * N + col) = v0;
                *reinterpret_cast<float2*>(C + (size_t)(row + 8) * N + col) = v1;
            }
        }
        // no barrier needed: next tile's prologue writes stages 0..2 only;
        // laggard warps can still be reading stage 3 (NC % 4 == 0).
    }
#undef ISSUE_STAGE
}

// ---------------------------------------------------------------------------
// Kernel 0: fused prologue.
// Block 0: softmax convolution coefficients. Blocks 1..: tf32 weight rounding.
// ---------------------------------------------------------------------------
__global__ void pre_kernel(const float* __restrict__ Wv,
                           const float* __restrict__ Wo) {
    if (blockIdx.x == 0) {
        __shared__ float warp_sum[8];
        const int t = threadIdx.x;
        const int lane = t & 31, warp = t >> 5;
        const float cc = -logf(10000.0f) / 384.0f;
        for (int d = 0; d <= DMAX; ++d) {
            float val = 0.f;
            for (int j = t; j < 384; j += 256)
                val += cosf((float)d * __expf(cc * (float)j));
#pragma unroll
            for (int o = 16; o; o >>= 1)
                val += __shfl_xor_sync(0xffffffffu, val, o);
            if (lane == 0) warp_sum[warp] = val;
            __syncthreads();
            if (t == 0) {
                float w = 0.f;
#pragma unroll
                for (int i = 0; i < 8; ++i) w += warp_sum[i];
                g_e[d] = expf(w - 384.0f);
            }
            __syncthreads();
        }
    } else {
        int i = (blockIdx.x - 1) * 256 + threadIdx.x;
        g_wv[i] = to_tf32_f(Wv[i]);
        g_wo[i] = to_tf32_f(Wo[i]);
    }
}

// ---------------------------------------------------------------------------
// Kernel 2: softmax == normalized 15-tap convolution along seq.
// Register sliding window: 4 consecutive rows per thread from an 18-row
// window. Output tf32-pre-rounded so gemm2 skips A-side cvt.
// ---------------------------------------------------------------------------
__global__ __launch_bounds__(256) void smooth_kernel() {
    const int NC4 = KV / 4;                       // 64
    int idx = blockIdx.x * blockDim.x + threadIdx.x;
    if (idx >= (MTOT / 4) * NC4) return;
    const int mg = idx >> 6;
    const int c  = idx & 63;
    const int m0 = mg << 2;
    const int s0 = m0 & (SEQ - 1);

    float earr[15];
#pragma unroll
    for (int t = 0; t < 15; ++t) earr[t] = g_e[t < 7 ? 7 - t : t - 7];

    const float4* vp = reinterpret_cast<const float4*>(g_v);
    float4 w[18];
#pragma unroll
    for (int j = 0; j < 18; ++j) {
        int s = s0 - 7 + j;
        if (s >= 0 && s < SEQ)
            w[j] = vp[(size_t)(m0 - 7 + j) * NC4 + c];
        else
            w[j] = make_float4(0.f, 0.f, 0.f, 0.f);
    }

    float4* ap = reinterpret_cast<float4*>(g_a);
#pragma unroll
    for (int i = 0; i < 4; ++i) {
        const int s = s0 + i;
        float4 acc = make_float4(0.f, 0.f, 0.f, 0.f);
        float z = 1.0f;
#pragma unroll
        for (int t = 0; t < 15; ++t) {
            const float e = earr[t];
            const float4 vv = w[i + t];
            acc.x += e * vv.x; acc.y += e * vv.y;
            acc.z += e * vv.z; acc.w += e * vv.w;
        }
#pragma unroll
        for (int d = 1; d <= DMAX; ++d) {
            if (s >= d)       z += g_e[d];
            if (s + d < SEQ)  z += g_e[d];
        }
        const float inv = 1.0f / z;
        float4 o;
        o.x = to_tf32_f(acc.x * inv); o.y = to_tf32_f(acc.y * inv);
        o.z = to_tf32_f(acc.z * inv); o.w = to_tf32_f(acc.w * inv);
        ap[(size_t)(m0 + i) * NC4 + c] = o;
    }
}

// ---------------------------------------------------------------------------
// Launch
// ---------------------------------------------------------------------------
extern "C" void kernel_launch(void* const* d_in, const int* in_sizes, int n_in,
                              void* d_out, int out_size) {
    const float* x  = (const float*)d_in[0];
    // d_in[1] = Wq, d_in[2] = Wk are dead (rope ignores its input)
    const float* Wv = (const float*)d_in[3];
    const float* Wo = (const float*)d_in[4];
    float* out = (float*)d_out;

    float* v_buf;  cudaGetSymbolAddress((void**)&v_buf, g_v);
    float* a_buf;  cudaGetSymbolAddress((void**)&a_buf, g_a);
    float* wv_buf; cudaGetSymbolAddress((void**)&wv_buf, g_wv);
    float* wo_buf; cudaGetSymbolAddress((void**)&wo_buf, g_wo);

    const int SMEM_BYTES = NSTAGE * STGB + 128;   // ~216 KB
    cudaFuncSetAttribute(gemm_tf32<true>,
                         cudaFuncAttributeMaxDynamicSharedMemorySize, SMEM_BYTES);
    cudaFuncSetAttribute(gemm_tf32<false>,
                         cudaFuncAttributeMaxDynamicSharedMemorySize, SMEM_BYTES);

    // 0) coefficients + weight pre-rounding (one fused launch)
    pre_kernel<<<1 + KV * HIDDEN / 256, 256>>>(Wv, Wo);

    // 1) v = x @ Wv^T : tiles = (16384/256)*(256/128) = 128 <= 148
    gemm_tf32<true><<<128, 512, SMEM_BYTES>>>(x, wv_buf, v_buf,
                                              MTOT, KV, HIDDEN);

    // 2) softmax(attn) @ v == normalized 15-tap convolution
    {
        int n = (MTOT / 4) * (KV / 4);
        smooth_kernel<<<(n + 255) / 256, 256>>>();
    }

    // 3) out = a @ Wo^T : tiles = 64*6 = 384, persistent over 148 CTAs
    gemm_tf32<false><<<NSM, 512, SMEM_BYTES>>>(a_buf, wo_buf, out,
                                               MTOT, HIDDEN, KV);
}

// round 12
// speedup vs baseline: 1.3949x; 1.3949x over previous
#include <cuda_runtime.h>
#include <cuda_fp16.h>
#include <math.h>
#include <stdint.h>

// Problem constants
#define SEQ     8192
#define BATCH   2
#define MTOT    (BATCH * SEQ)   // 16384
#define HIDDEN  768
#define KV      256
#define DMAX    7
#define NSM     148

// Scratch (static __device__ — no runtime allocation allowed)
__device__ float g_e[DMAX + 1];
__device__ __align__(16) float  g_v[MTOT * KV];          // gemm1 out (fp32)
__device__ __align__(16) __half g_ah[MTOT * KV];         // smooth out (fp16)
__device__ __align__(16) __half g_xh[MTOT * HIDDEN];     // x in fp16
__device__ __align__(16) __half g_wvh[KV * HIDDEN];      // Wv in fp16
__device__ __align__(16) __half g_woh[HIDDEN * KV];      // Wo in fp16

// ---------------------------------------------------------------------------
// helpers
// ---------------------------------------------------------------------------
__device__ __forceinline__ uint32_t smem_u32(const void* p) {
    uint32_t a;
    asm("{ .reg .u64 t; cvta.to.shared.u64 t, %1; cvt.u32.u64 %0, t; }"
        : "=r"(a) : "l"(p));
    return a;
}

__device__ __forceinline__ void ldsm4(uint32_t* r, uint32_t addr) {
    asm volatile("ldmatrix.sync.aligned.m8n8.x4.shared.b16 {%0,%1,%2,%3}, [%4];"
        : "=r"(r[0]), "=r"(r[1]), "=r"(r[2]), "=r"(r[3]) : "r"(addr));
}

__device__ __forceinline__ void mma_f16(float* d, const uint32_t* a,
                                        const uint32_t* b) {
    asm volatile(
        "mma.sync.aligned.m16n8k16.row.col.f32.f16.f16.f32 "
        "{%0,%1,%2,%3}, {%4,%5,%6,%7}, {%8,%9}, {%0,%1,%2,%3};"
        : "+f"(d[0]), "+f"(d[1]), "+f"(d[2]), "+f"(d[3])
        : "r"(a[0]), "r"(a[1]), "r"(a[2]), "r"(a[3]), "r"(b[0]), "r"(b[1]));
}

#define CP_ASYNC16(dst, src) \
    asm volatile("cp.async.cg.shared.global [%0], [%1], 16;" \
                 :: "r"(dst), "l"(src) : "memory")
#define CP_COMMIT() asm volatile("cp.async.commit_group;" ::: "memory")
#define CP_WAIT2()  asm volatile("cp.async.wait_group 2;" ::: "memory")
#define CP_WAIT0()  asm volatile("cp.async.wait_group 0;" ::: "memory")

// fp16 tile geometry: 64B rows (32 fp16 per K=32 chunk), XOR swizzle
// (R4-verified conflict-free for ldmatrix / cp.async 16B granularity)
#define ASZH   (256 * 64)                 // A tile bytes: 16384
#define BSZH   (128 * 64)                 // B tile bytes: 8192
#define STGH   (ASZH + BSZH)              // 24576 per stage
#define NSTAGE 4                          // 96 KB total

__device__ __forceinline__ uint32_t swz(int row, int kg) {
    return (uint32_t)(row * 64) +
           ((uint32_t)((kg ^ (row & 3) ^ ((row & 4) >> 1)) & 3) << 4);
}

// ---------------------------------------------------------------------------
// Persistent-CTA FP16 GEMM (NT): C[m,n] = sum_k A[m*K+k]*B[n*K+k]
// fp16 in (pre-converted), fp32 out; m16n8k16 mma (half the instructions of
// tf32 m16n8k8 at the same mantissa width). CTA tile 256x128, 512 threads
// (16 warps 4x4), warp tile 64x32. 4-stage cp.async pipeline, one
// __syncthreads per chunk, fragment double-buffering across the two
// k16-steps. Grid = min(tiles, NSM). NC ≡ 0 mod NSTAGE required.
// ---------------------------------------------------------------------------
__global__ __launch_bounds__(512, 1) void gemm_fp16(
    const __half* __restrict__ A, const __half* __restrict__ B,
    float* __restrict__ C, int M, int N, int K)
{
    extern __shared__ char dynsmem[];
    const uint32_t sb = (smem_u32(dynsmem) + 127u) & ~127u;

    const int tid  = threadIdx.x;
    const int wid  = tid >> 5;
    const int lane = tid & 31;
    const int NC   = K >> 5;
    const int nTilesN = N >> 7;
    const int nTiles  = (M >> 8) * nTilesN;

    const int warpM = (wid >> 2) * 64;
    const int warpN = (wid & 3) * 32;

    // cp.async mapping (tile-relative)
    const int ra = tid >> 1, ha = tid & 1;     // A: 2 thr/row, 2x16B each
    const int rb = tid >> 2, qb = tid & 3;     // B: 4 thr/row, 1x16B each
    const uint32_t dA0 = swz(ra, 2 * ha);
    const uint32_t dA1 = swz(ra, 2 * ha + 1);
    const uint32_t dB0 = swz(rb, qb);

    // ldmatrix lane components (R4-verified fragment layout)
    const int laRow = warpM + (lane & 15);
    const int laKg  = lane >> 4;
    const int lbRow = warpN + (lane & 7) + ((lane & 16) >> 1);
    const int lbKg  = (lane >> 3) & 1;

#define ISSUE_STAGE(stg, kt)                                              \
    do {                                                                  \
        uint32_t bs = sb + (uint32_t)(stg) * STGH;                        \
        const __half* pa = gA + (kt);                                     \
        const __half* pb = gB + (kt);                                     \
        CP_ASYNC16(bs + dA0, pa);                                         \
        CP_ASYNC16(bs + dA1, pa + 8);                                     \
        CP_ASYNC16(bs + ASZH + dB0, pb);                                  \
        CP_COMMIT();                                                      \
    } while (0)

    for (int t = blockIdx.x; t < nTiles; t += gridDim.x) {
        const int bm = (t / nTilesN) * 256;
        const int bn = (t - (t / nTilesN) * nTilesN) * 128;

        const __half* gA = A + (size_t)(bm + ra) * K + ha * 16;
        const __half* gB = B + (size_t)(bn + rb) * K + qb * 8;

        float acc[4][4][4];
#pragma unroll
        for (int i = 0; i < 4; ++i)
#pragma unroll
            for (int j = 0; j < 4; ++j)
#pragma unroll
                for (int q = 0; q < 4; ++q) acc[i][j][q] = 0.f;

        ISSUE_STAGE(0, 0);
        ISSUE_STAGE(1, 32);
        ISSUE_STAGE(2, 64);

        int stage = 0;
        for (int c = 0; c < NC; ++c) {
            CP_WAIT2();
            __syncthreads();

            if (c + 3 < NC) {
                int ns = stage + 3; if (ns >= NSTAGE) ns -= NSTAGE;
                ISSUE_STAGE(ns, (c + 3) * 32);
            }

            const uint32_t sA = sb + (uint32_t)stage * STGH;
            const uint32_t sB = sA + ASZH;

            uint32_t af[2][4][4], bf[2][2][4];
#pragma unroll
            for (int mt = 0; mt < 4; ++mt)
                ldsm4(af[0][mt], sA + swz(laRow + mt * 16, laKg));
            ldsm4(bf[0][0], sB + swz(lbRow,      lbKg));
            ldsm4(bf[0][1], sB + swz(lbRow + 16, lbKg));

#pragma unroll
            for (int ks = 0; ks < 2; ++ks) {
                const int cur = ks & 1;
                if (ks == 0) {
#pragma unroll
                    for (int mt = 0; mt < 4; ++mt)
                        ldsm4(af[1][mt], sA + swz(laRow + mt * 16, 2 + laKg));
                    ldsm4(bf[1][0], sB + swz(lbRow,      2 + lbKg));
                    ldsm4(bf[1][1], sB + swz(lbRow + 16, 2 + lbKg));
                }
#pragma unroll
                for (int mt = 0; mt < 4; ++mt)
#pragma unroll
                    for (int nt = 0; nt < 4; ++nt)
                        mma_f16(acc[mt][nt], af[cur][mt],
                                &bf[cur][nt >> 1][(nt & 1) * 2]);
            }

            if (++stage >= NSTAGE) stage = 0;
        }
        CP_WAIT0();

        // epilogue: direct global stores
#pragma unroll
        for (int mt = 0; mt < 4; ++mt) {
#pragma unroll
            for (int nt = 0; nt < 4; ++nt) {
                int row = bm + warpM + mt * 16 + (lane >> 2);
                int col = bn + warpN + nt * 8 + (lane & 3) * 2;
                float2 v0 = make_float2(acc[mt][nt][0], acc[mt][nt][1]);
                float2 v1 = make_float2(acc[mt][nt][2], acc[mt][nt][3]);
                *reinterpret_cast<float2*>(C + (size_t)row * N + col) = v0;
                *reinterpret_cast<float2*>(C + (size_t)(row + 8) * N + col) = v1;
            }
        }
        // safe tile transition: next prologue writes stages 0..2; laggards
        // only read stage 3 (NC % 4 == 0).
    }
#undef ISSUE_STAGE
}

// ---------------------------------------------------------------------------
// Kernel 0: fused prologue.
// Block 0: coefficients. Blocks 1..768: weights -> fp16.
// Blocks 769..13056: x -> fp16 (4 elts/thread).
// ---------------------------------------------------------------------------
#define WBLK (KV * HIDDEN / 256)            // 768
#define XBLK (MTOT * HIDDEN / 1024)         // 12288

__global__ void pre_kernel(const float* __restrict__ x,
                           const float* __restrict__ Wv,
                           const float* __restrict__ Wo) {
    const int b = blockIdx.x;
    if (b == 0) {
        __shared__ float warp_sum[8];
        const int t = threadIdx.x;
        const int lane = t & 31, warp = t >> 5;
        const float cc = -logf(10000.0f) / 384.0f;
        for (int d = 0; d <= DMAX; ++d) {
            float val = 0.f;
            for (int j = t; j < 384; j += 256)
                val += cosf((float)d * __expf(cc * (float)j));
#pragma unroll
            for (int o = 16; o; o >>= 1)
                val += __shfl_xor_sync(0xffffffffu, val, o);
            if (lane == 0) warp_sum[warp] = val;
            __syncthreads();
            if (t == 0) {
                float w = 0.f;
#pragma unroll
                for (int i = 0; i < 8; ++i) w += warp_sum[i];
                g_e[d] = expf(w - 384.0f);
            }
            __syncthreads();
        }
    } else if (b <= WBLK) {
        int i = (b - 1) * 256 + threadIdx.x;
        g_wvh[i] = __float2half_rn(Wv[i]);
        g_woh[i] = __float2half_rn(Wo[i]);
    } else {
        int i = (b - 1 - WBLK) * 1024 + threadIdx.x * 4;
        float4 v = *reinterpret_cast<const float4*>(x + i);
        __half2 h0 = __floats2half2_rn(v.x, v.y);
        __half2 h1 = __floats2half2_rn(v.z, v.w);
        uint2 o;
        o.x = *reinterpret_cast<uint32_t*>(&h0);
        o.y = *reinterpret_cast<uint32_t*>(&h1);
        *reinterpret_cast<uint2*>(g_xh + i) = o;
    }
}

// ---------------------------------------------------------------------------
// Kernel 2: softmax == normalized 15-tap convolution along seq.
// Register sliding window (4 rows / thread). Emits fp16 directly for gemm2.
// ---------------------------------------------------------------------------
__global__ __launch_bounds__(256) void smooth_kernel() {
    const int NC4 = KV / 4;                       // 64
    int idx = blockIdx.x * blockDim.x + threadIdx.x;
    if (idx >= (MTOT / 4) * NC4) return;
    const int mg = idx >> 6;
    const int c  = idx & 63;
    const int m0 = mg << 2;
    const int s0 = m0 & (SEQ - 1);

    float earr[15];
#pragma unroll
    for (int t = 0; t < 15; ++t) earr[t] = g_e[t < 7 ? 7 - t : t - 7];

    const float4* vp = reinterpret_cast<const float4*>(g_v);
    float4 w[18];
#pragma unroll
    for (int j = 0; j < 18; ++j) {
        int s = s0 - 7 + j;
        if (s >= 0 && s < SEQ)
            w[j] = vp[(size_t)(m0 - 7 + j) * NC4 + c];
        else
            w[j] = make_float4(0.f, 0.f, 0.f, 0.f);
    }

#pragma unroll
    for (int i = 0; i < 4; ++i) {
        const int s = s0 + i;
        float4 acc = make_float4(0.f, 0.f, 0.f, 0.f);
        float z = 1.0f;
#pragma unroll
        for (int t = 0; t < 15; ++t) {
            const float e = earr[t];
            const float4 vv = w[i + t];
            acc.x += e * vv.x; acc.y += e * vv.y;
            acc.z += e * vv.z; acc.w += e * vv.w;
        }
#pragma unroll
        for (int d = 1; d <= DMAX; ++d) {
            if (s >= d)       z += g_e[d];
            if (s + d < SEQ)  z += g_e[d];
        }
        const float inv = 1.0f / z;
        __half2 h0 = __floats2half2_rn(acc.x * inv, acc.y * inv);
        __half2 h1 = __floats2half2_rn(acc.z * inv, acc.w * inv);
        uint2 o;
        o.x = *reinterpret_cast<uint32_t*>(&h0);
        o.y = *reinterpret_cast<uint32_t*>(&h1);
        *reinterpret_cast<uint2*>(g_ah + (size_t)(m0 + i) * KV + c * 4) = o;
    }
}

// ---------------------------------------------------------------------------
// Launch
// ---------------------------------------------------------------------------
extern "C" void kernel_launch(void* const* d_in, const int* in_sizes, int n_in,
                              void* d_out, int out_size) {
    const float* x  = (const float*)d_in[0];
    // d_in[1] = Wq, d_in[2] = Wk are dead (rope ignores its input)
    const float* Wv = (const float*)d_in[3];
    const float* Wo = (const float*)d_in[4];
    float* out = (float*)d_out;

    float*  v_buf;  cudaGetSymbolAddress((void**)&v_buf,  g_v);
    __half* ah_buf; cudaGetSymbolAddress((void**)&ah_buf, g_ah);
    __half* xh_buf; cudaGetSymbolAddress((void**)&xh_buf, g_xh);
    __half* wv_buf; cudaGetSymbolAddress((void**)&wv_buf, g_wvh);
    __half* wo_buf; cudaGetSymbolAddress((void**)&wo_buf, g_woh);

    const int SMEM_BYTES = NSTAGE * STGH + 128;   // ~96 KB
    cudaFuncSetAttribute(gemm_fp16,
                         cudaFuncAttributeMaxDynamicSharedMemorySize, SMEM_BYTES);

    // 0) coefficients + fp16 pre-conversion of Wv, Wo, x (one launch)
    pre_kernel<<<1 + WBLK + XBLK, 256>>>(x, Wv, Wo);

    // 1) v = x @ Wv^T : tiles = 64*2 = 128 <= 148
    gemm_fp16<<<128, 512, SMEM_BYTES>>>(xh_buf, wv_buf, v_buf,
                                        MTOT, KV, HIDDEN);

    // 2) softmax(attn) @ v == normalized 15-tap convolution (fp16 out)
    {
        int n = (MTOT / 4) * (KV / 4);
        smooth_kernel<<<(n + 255) / 256, 256>>>();
    }

    // 3) out = a @ Wo^T : tiles = 64*6 = 384, persistent over 148 CTAs
    gemm_fp16<<<NSM, 512, SMEM_BYTES>>>(ah_buf, wo_buf, out,
                                        MTOT, HIDDEN, KV);
}

// round 13
// speedup vs baseline: 1.6468x; 1.1806x over previous
#include <cuda_runtime.h>
#include <cuda_fp16.h>
#include <math.h>
#include <stdint.h>

// Problem constants
#define SEQ     8192
#define BATCH   2
#define MTOT    (BATCH * SEQ)   // 16384
#define HIDDEN  768
#define KV      256
#define DMAX    7
#define NSM     148

// Scratch (static __device__ — no runtime allocation allowed)
__device__ float g_e[DMAX + 1];
__device__ __align__(16) float  g_v[MTOT * KV];          // gemm1 out (fp32)
__device__ __align__(16) __half g_ah[MTOT * KV];         // smooth out (fp16)
__device__ __align__(16) __half g_xh[MTOT * HIDDEN];     // x in fp16
__device__ __align__(16) __half g_wvh[KV * HIDDEN];      // Wv in fp16
__device__ __align__(16) __half g_woh[HIDDEN * KV];      // Wo in fp16

// ---------------------------------------------------------------------------
// helpers
// ---------------------------------------------------------------------------
__device__ __forceinline__ uint32_t smem_u32(const void* p) {
    uint32_t a;
    asm("{ .reg .u64 t; cvta.to.shared.u64 t, %1; cvt.u32.u64 %0, t; }"
        : "=r"(a) : "l"(p));
    return a;
}

__device__ __forceinline__ void ldsm4(uint32_t* r, uint32_t addr) {
    asm volatile("ldmatrix.sync.aligned.m8n8.x4.shared.b16 {%0,%1,%2,%3}, [%4];"
        : "=r"(r[0]), "=r"(r[1]), "=r"(r[2]), "=r"(r[3]) : "r"(addr));
}

__device__ __forceinline__ void mma_f16(float* d, const uint32_t* a,
                                        const uint32_t* b) {
    asm volatile(
        "mma.sync.aligned.m16n8k16.row.col.f32.f16.f16.f32 "
        "{%0,%1,%2,%3}, {%4,%5,%6,%7}, {%8,%9}, {%0,%1,%2,%3};"
        : "+f"(d[0]), "+f"(d[1]), "+f"(d[2]), "+f"(d[3])
        : "r"(a[0]), "r"(a[1]), "r"(a[2]), "r"(a[3]), "r"(b[0]), "r"(b[1]));
}

#define CP_ASYNC16(dst, src) \
    asm volatile("cp.async.cg.shared.global [%0], [%1], 16;" \
                 :: "r"(dst), "l"(src) : "memory")
#define CP_COMMIT() asm volatile("cp.async.commit_group;" ::: "memory")
#define CP_WAIT1()  asm volatile("cp.async.wait_group 1;" ::: "memory")
#define CP_WAIT0()  asm volatile("cp.async.wait_group 0;" ::: "memory")

// fp16 tile geometry: BK=64 -> 128B rows (64 fp16), 8-group XOR swizzle.
// ldmatrix: 8 rows of one matrix use distinct 16B offsets -> conflict-free.
#define ASZH   (256 * 128)                // A tile bytes: 32768
#define BSZH   (128 * 128)                // B tile bytes: 16384
#define STGH   (ASZH + BSZH)              // 49152 per stage
#define NSTAGE 3                          // 144 KB total

__device__ __forceinline__ uint32_t swz(int row, int kg) {
    return (uint32_t)(row * 128) + ((uint32_t)((kg ^ row) & 7) << 4);
}

// ---------------------------------------------------------------------------
// Persistent-CTA FP16 GEMM (NT): C[m,n] = sum_k A[m*K+k]*B[n*K+k]
// fp16 in (pre-converted), fp32 out; m16n8k16. CTA tile 256x128, 512 threads
// (16 warps 4x4), warp tile 64x32. BK=64 per chunk: 128 MMAs + 24 LDSM per
// warp between barriers (halved per-chunk overhead vs BK=32).
// 3-stage cp.async pipeline (prefetch distance 2), one __syncthreads per
// chunk + one per tile transition. K multiple of 64.
// ---------------------------------------------------------------------------
__global__ __launch_bounds__(512, 1) void gemm_fp16(
    const __half* __restrict__ A, const __half* __restrict__ B,
    float* __restrict__ C, int M, int N, int K)
{
    extern __shared__ char dynsmem[];
    const uint32_t sb = (smem_u32(dynsmem) + 127u) & ~127u;

    const int tid  = threadIdx.x;
    const int wid  = tid >> 5;
    const int lane = tid & 31;
    const int NC   = K >> 6;                    // 64-wide K chunks
    const int nTilesN = N >> 7;
    const int nTiles  = (M >> 8) * nTilesN;

    const int warpM = (wid >> 2) * 64;
    const int warpN = (wid & 3) * 32;

    // cp.async mapping (tile-relative)
    const int ra = tid >> 1, ha = tid & 1;     // A: 2 thr/row, 4x16B each
    const int rb = tid >> 2, qb = tid & 3;     // B: 4 thr/row, 2x16B each
    uint32_t dAo[4], dBo[2];
#pragma unroll
    for (int i = 0; i < 4; ++i) dAo[i] = swz(ra, ha * 4 + i);
#pragma unroll
    for (int i = 0; i < 2; ++i) dBo[i] = swz(rb, qb * 2 + i);

    // ldmatrix lane components
    const int laRow = warpM + (lane & 15);
    const int laKg  = lane >> 4;
    const int lbRow = warpN + (lane & 7) + ((lane & 16) >> 1);
    const int lbKg  = (lane >> 3) & 1;

#define ISSUE_STAGE(stg, kt)                                              \
    do {                                                                  \
        uint32_t bs = sb + (uint32_t)(stg) * STGH;                        \
        const __half* pa = gA + (kt);                                     \
        const __half* pb = gB + (kt);                                     \
        CP_ASYNC16(bs + dAo[0], pa);                                      \
        CP_ASYNC16(bs + dAo[1], pa + 8);                                  \
        CP_ASYNC16(bs + dAo[2], pa + 16);                                 \
        CP_ASYNC16(bs + dAo[3], pa + 24);                                 \
        CP_ASYNC16(bs + ASZH + dBo[0], pb);                               \
        CP_ASYNC16(bs + ASZH + dBo[1], pb + 8);                           \
        CP_COMMIT();                                                      \
    } while (0)

    for (int t = blockIdx.x; t < nTiles; t += gridDim.x) {
        const int bm = (t / nTilesN) * 256;
        const int bn = (t - (t / nTilesN) * nTilesN) * 128;

        const __half* gA = A + (size_t)(bm + ra) * K + ha * 32;
        const __half* gB = B + (size_t)(bn + rb) * K + qb * 16;

        float acc[4][4][4];
#pragma unroll
        for (int i = 0; i < 4; ++i)
#pragma unroll
            for (int j = 0; j < 4; ++j)
#pragma unroll
                for (int q = 0; q < 4; ++q) acc[i][j][q] = 0.f;

        ISSUE_STAGE(0, 0);
        ISSUE_STAGE(1, 64);

        int stage = 0;
        for (int c = 0; c < NC; ++c) {
            CP_WAIT1();
            __syncthreads();

            if (c + 2 < NC) {
                int ns = stage + 2; if (ns >= NSTAGE) ns -= NSTAGE;
                ISSUE_STAGE(ns, (c + 2) * 64);
            }

            const uint32_t sA = sb + (uint32_t)stage * STGH;
            const uint32_t sB = sA + ASZH;

            uint32_t af[2][4][4], bf[2][2][4];
#pragma unroll
            for (int mt = 0; mt < 4; ++mt)
                ldsm4(af[0][mt], sA + swz(laRow + mt * 16, laKg));
            ldsm4(bf[0][0], sB + swz(lbRow,      lbKg));
            ldsm4(bf[0][1], sB + swz(lbRow + 16, lbKg));

#pragma unroll
            for (int ks = 0; ks < 4; ++ks) {
                const int cur = ks & 1;
                if (ks < 3) {
                    const int kg = 2 * (ks + 1);
#pragma unroll
                    for (int mt = 0; mt < 4; ++mt)
                        ldsm4(af[cur ^ 1][mt],
                              sA + swz(laRow + mt * 16, kg + laKg));
                    ldsm4(bf[cur ^ 1][0], sB + swz(lbRow,      kg + lbKg));
                    ldsm4(bf[cur ^ 1][1], sB + swz(lbRow + 16, kg + lbKg));
                }
#pragma unroll
                for (int mt = 0; mt < 4; ++mt)
#pragma unroll
                    for (int nt = 0; nt < 4; ++nt)
                        mma_f16(acc[mt][nt], af[cur][mt],
                                &bf[cur][nt >> 1][(nt & 1) * 2]);
            }

            if (++stage >= NSTAGE) stage = 0;
        }
        CP_WAIT0();

        // epilogue: direct global stores
#pragma unroll
        for (int mt = 0; mt < 4; ++mt) {
#pragma unroll
            for (int nt = 0; nt < 4; ++nt) {
                int row = bm + warpM + mt * 16 + (lane >> 2);
                int col = bn + warpN + nt * 8 + (lane & 3) * 2;
                float2 v0 = make_float2(acc[mt][nt][0], acc[mt][nt][1]);
                float2 v1 = make_float2(acc[mt][nt][2], acc[mt][nt][3]);
                *reinterpret_cast<float2*>(C + (size_t)row * N + col) = v0;
                *reinterpret_cast<float2*>(C + (size_t)(row + 8) * N + col) = v1;
            }
        }
        __syncthreads();   // tile transition: all smem reads done before
                           // next tile's prologue overwrites stages 0/1
    }
#undef ISSUE_STAGE
}

// ---------------------------------------------------------------------------
// Kernel 0: fused prologue.
// Block 0: coefficients. Blocks 1..768: weights -> fp16.
// Blocks 769..: x -> fp16 (4 elts/thread).
// ---------------------------------------------------------------------------
#define WBLK (KV * HIDDEN / 256)            // 768
#define XBLK (MTOT * HIDDEN / 1024)         // 12288

__global__ void pre_kernel(const float* __restrict__ x,
                           const float* __restrict__ Wv,
                           const float* __restrict__ Wo) {
    const int b = blockIdx.x;
    if (b == 0) {
        __shared__ float warp_sum[8];
        const int t = threadIdx.x;
        const int lane = t & 31, warp = t >> 5;
        const float cc = -logf(10000.0f) / 384.0f;
        for (int d = 0; d <= DMAX; ++d) {
            float val = 0.f;
            for (int j = t; j < 384; j += 256)
                val += cosf((float)d * __expf(cc * (float)j));
#pragma unroll
            for (int o = 16; o; o >>= 1)
                val += __shfl_xor_sync(0xffffffffu, val, o);
            if (lane == 0) warp_sum[warp] = val;
            __syncthreads();
            if (t == 0) {
                float w = 0.f;
#pragma unroll
                for (int i = 0; i < 8; ++i) w += warp_sum[i];
                g_e[d] = expf(w - 384.0f);
            }
            __syncthreads();
        }
    } else if (b <= WBLK) {
        int i = (b - 1) * 256 + threadIdx.x;
        g_wvh[i] = __float2half_rn(Wv[i]);
        g_woh[i] = __float2half_rn(Wo[i]);
    } else {
        int i = (b - 1 - WBLK) * 1024 + threadIdx.x * 4;
        float4 v = *reinterpret_cast<const float4*>(x + i);
        __half2 h0 = __floats2half2_rn(v.x, v.y);
        __half2 h1 = __floats2half2_rn(v.z, v.w);
        uint2 o;
        o.x = *reinterpret_cast<uint32_t*>(&h0);
        o.y = *reinterpret_cast<uint32_t*>(&h1);
        *reinterpret_cast<uint2*>(g_xh + i) = o;
    }
}

// ---------------------------------------------------------------------------
// Kernel 2: softmax == normalized 15-tap convolution along seq.
// Register sliding window (4 rows / thread). Emits fp16 directly for gemm2.
// ---------------------------------------------------------------------------
__global__ __launch_bounds__(256) void smooth_kernel() {
    const int NC4 = KV / 4;                       // 64
    int idx = blockIdx.x * blockDim.x + threadIdx.x;
    if (idx >= (MTOT / 4) * NC4) return;
    const int mg = idx >> 6;
    const int c  = idx & 63;
    const int m0 = mg << 2;
    const int s0 = m0 & (SEQ - 1);

    float earr[15];
#pragma unroll
    for (int t = 0; t < 15; ++t) earr[t] = g_e[t < 7 ? 7 - t : t - 7];

    const float4* vp = reinterpret_cast<const float4*>(g_v);
    float4 w[18];
#pragma unroll
    for (int j = 0; j < 18; ++j) {
        int s = s0 - 7 + j;
        if (s >= 0 && s < SEQ)
            w[j] = vp[(size_t)(m0 - 7 + j) * NC4 + c];
        else
            w[j] = make_float4(0.f, 0.f, 0.f, 0.f);
    }

#pragma unroll
    for (int i = 0; i < 4; ++i) {
        const int s = s0 + i;
        float4 acc = make_float4(0.f, 0.f, 0.f, 0.f);
        float z = 1.0f;
#pragma unroll
        for (int t = 0; t < 15; ++t) {
            const float e = earr[t];
            const float4 vv = w[i + t];
            acc.x += e * vv.x; acc.y += e * vv.y;
            acc.z += e * vv.z; acc.w += e * vv.w;
        }
#pragma unroll
        for (int d = 1; d <= DMAX; ++d) {
            if (s >= d)       z += g_e[d];
            if (s + d < SEQ)  z += g_e[d];
        }
        const float inv = 1.0f / z;
        __half2 h0 = __floats2half2_rn(acc.x * inv, acc.y * inv);
        __half2 h1 = __floats2half2_rn(acc.z * inv, acc.w * inv);
        uint2 o;
        o.x = *reinterpret_cast<uint32_t*>(&h0);
        o.y = *reinterpret_cast<uint32_t*>(&h1);
        *reinterpret_cast<uint2*>(g_ah + (size_t)(m0 + i) * KV + c * 4) = o;
    }
}

// ---------------------------------------------------------------------------
// Launch
// ---------------------------------------------------------------------------
extern "C" void kernel_launch(void* const* d_in, const int* in_sizes, int n_in,
                              void* d_out, int out_size) {
    const float* x  = (const float*)d_in[0];
    // d_in[1] = Wq, d_in[2] = Wk are dead (rope ignores its input)
    const float* Wv = (const float*)d_in[3];
    const float* Wo = (const float*)d_in[4];
    float* out = (float*)d_out;

    float*  v_buf;  cudaGetSymbolAddress((void**)&v_buf,  g_v);
    __half* ah_buf; cudaGetSymbolAddress((void**)&ah_buf, g_ah);
    __half* xh_buf; cudaGetSymbolAddress((void**)&xh_buf, g_xh);
    __half* wv_buf; cudaGetSymbolAddress((void**)&wv_buf, g_wvh);
    __half* wo_buf; cudaGetSymbolAddress((void**)&wo_buf, g_woh);

    const int SMEM_BYTES = NSTAGE * STGH + 128;   // ~144 KB
    cudaFuncSetAttribute(gemm_fp16,
                         cudaFuncAttributeMaxDynamicSharedMemorySize, SMEM_BYTES);

    // 0) coefficients + fp16 pre-conversion of Wv, Wo, x (one launch)
    pre_kernel<<<1 + WBLK + XBLK, 256>>>(x, Wv, Wo);

    // 1) v = x @ Wv^T : tiles = 64*2 = 128 <= 148  (K=768 -> NC=12)
    gemm_fp16<<<128, 512, SMEM_BYTES>>>(xh_buf, wv_buf, v_buf,
                                        MTOT, KV, HIDDEN);

    // 2) softmax(attn) @ v == normalized 15-tap convolution (fp16 out)
    {
        int n = (MTOT / 4) * (KV / 4);
        smooth_kernel<<<(n + 255) / 256, 256>>>();
    }

    // 3) out = a @ Wo^T : tiles = 64*6 = 384, persistent (K=256 -> NC=4)
    gemm_fp16<<<NSM, 512, SMEM_BYTES>>>(ah_buf, wo_buf, out,
                                        MTOT, HIDDEN, KV);
}

// round 14
// speedup vs baseline: 1.6549x; 1.0049x over previous
#include <cuda_runtime.h>
#include <cuda_fp16.h>
#include <math.h>
#include <stdint.h>

// Problem constants
#define SEQ     8192
#define BATCH   2
#define MTOT    (BATCH * SEQ)   // 16384
#define HIDDEN  768
#define KV      256
#define DMAX    7
#define NSM     148

// Scratch (static __device__ — no runtime allocation allowed)
__device__ float g_e[DMAX + 1];
__device__ __align__(16) __half g_vh[MTOT * KV];         // gemm1 out (fp16)
__device__ __align__(16) __half g_ah[MTOT * KV];         // smooth out (fp16)
__device__ __align__(16) __half g_xh[MTOT * HIDDEN];     // x in fp16
__device__ __align__(16) __half g_wvh[KV * HIDDEN];      // Wv in fp16
__device__ __align__(16) __half g_woh[HIDDEN * KV];      // Wo in fp16

// ---------------------------------------------------------------------------
// helpers
// ---------------------------------------------------------------------------
__device__ __forceinline__ uint32_t smem_u32(const void* p) {
    uint32_t a;
    asm("{ .reg .u64 t; cvta.to.shared.u64 t, %1; cvt.u32.u64 %0, t; }"
        : "=r"(a) : "l"(p));
    return a;
}

__device__ __forceinline__ void ldsm4(uint32_t* r, uint32_t addr) {
    asm volatile("ldmatrix.sync.aligned.m8n8.x4.shared.b16 {%0,%1,%2,%3}, [%4];"
        : "=r"(r[0]), "=r"(r[1]), "=r"(r[2]), "=r"(r[3]) : "r"(addr));
}

__device__ __forceinline__ void mma_f16(float* d, const uint32_t* a,
                                        const uint32_t* b) {
    asm volatile(
        "mma.sync.aligned.m16n8k16.row.col.f32.f16.f16.f32 "
        "{%0,%1,%2,%3}, {%4,%5,%6,%7}, {%8,%9}, {%0,%1,%2,%3};"
        : "+f"(d[0]), "+f"(d[1]), "+f"(d[2]), "+f"(d[3])
        : "r"(a[0]), "r"(a[1]), "r"(a[2]), "r"(a[3]), "r"(b[0]), "r"(b[1]));
}

#define CP_ASYNC16(dst, src) \
    asm volatile("cp.async.cg.shared.global [%0], [%1], 16;" \
                 :: "r"(dst), "l"(src) : "memory")
#define CP_COMMIT() asm volatile("cp.async.commit_group;" ::: "memory")
#define CP_WAIT1()  asm volatile("cp.async.wait_group 1;" ::: "memory")
#define CP_WAIT0()  asm volatile("cp.async.wait_group 0;" ::: "memory")

// fp16 tile geometry: BK=64 -> 128B rows (64 fp16), 8-group XOR swizzle.
#define ASZH   (256 * 128)                // A tile bytes: 32768
#define BSZH   (128 * 128)                // B tile bytes: 16384
#define STGH   (ASZH + BSZH)              // 49152 per stage
#define NSTAGE 3                          // 144 KB total

__device__ __forceinline__ uint32_t swz(int row, int kg) {
    return (uint32_t)(row * 128) + ((uint32_t)((kg ^ row) & 7) << 4);
}

// ---------------------------------------------------------------------------
// Persistent-CTA FP16 GEMM (NT): C[m,n] = sum_k A[m*K+k]*B[n*K+k]
// fp16 in (pre-converted); HALF_OUT selects fp16 vs fp32 output.
// CTA tile 256x128, 512 threads (16 warps 4x4), warp tile 64x32, m16n8k16,
// BK=64 per chunk (128 MMAs + 24 LDSM per warp between barriers).
// 3-stage cp.async pipeline, fragment double-buffering. K multiple of 64.
// ---------------------------------------------------------------------------
template <bool HALF_OUT>
__global__ __launch_bounds__(512, 1) void gemm_fp16(
    const __half* __restrict__ A, const __half* __restrict__ B,
    void* __restrict__ Cv, int M, int N, int K)
{
    extern __shared__ char dynsmem[];
    const uint32_t sb = (smem_u32(dynsmem) + 127u) & ~127u;

    const int tid  = threadIdx.x;
    const int wid  = tid >> 5;
    const int lane = tid & 31;
    const int NC   = K >> 6;
    const int nTilesN = N >> 7;
    const int nTiles  = (M >> 8) * nTilesN;

    const int warpM = (wid >> 2) * 64;
    const int warpN = (wid & 3) * 32;

    // cp.async mapping (tile-relative)
    const int ra = tid >> 1, ha = tid & 1;     // A: 2 thr/row, 4x16B each
    const int rb = tid >> 2, qb = tid & 3;     // B: 4 thr/row, 2x16B each
    uint32_t dAo[4], dBo[2];
#pragma unroll
    for (int i = 0; i < 4; ++i) dAo[i] = swz(ra, ha * 4 + i);
#pragma unroll
    for (int i = 0; i < 2; ++i) dBo[i] = swz(rb, qb * 2 + i);

    // ldmatrix lane components
    const int laRow = warpM + (lane & 15);
    const int laKg  = lane >> 4;
    const int lbRow = warpN + (lane & 7) + ((lane & 16) >> 1);
    const int lbKg  = (lane >> 3) & 1;

#define ISSUE_STAGE(stg, kt)                                              \
    do {                                                                  \
        uint32_t bs = sb + (uint32_t)(stg) * STGH;                        \
        const __half* pa = gA + (kt);                                     \
        const __half* pb = gB + (kt);                                     \
        CP_ASYNC16(bs + dAo[0], pa);                                      \
        CP_ASYNC16(bs + dAo[1], pa + 8);                                  \
        CP_ASYNC16(bs + dAo[2], pa + 16);                                 \
        CP_ASYNC16(bs + dAo[3], pa + 24);                                 \
        CP_ASYNC16(bs + ASZH + dBo[0], pb);                               \
        CP_ASYNC16(bs + ASZH + dBo[1], pb + 8);                           \
        CP_COMMIT();                                                      \
    } while (0)

    for (int t = blockIdx.x; t < nTiles; t += gridDim.x) {
        const int bm = (t / nTilesN) * 256;
        const int bn = (t - (t / nTilesN) * nTilesN) * 128;

        const __half* gA = A + (size_t)(bm + ra) * K + ha * 32;
        const __half* gB = B + (size_t)(bn + rb) * K + qb * 16;

        float acc[4][4][4];
#pragma unroll
        for (int i = 0; i < 4; ++i)
#pragma unroll
            for (int j = 0; j < 4; ++j)
#pragma unroll
                for (int q = 0; q < 4; ++q) acc[i][j][q] = 0.f;

        ISSUE_STAGE(0, 0);
        ISSUE_STAGE(1, 64);

        int stage = 0;
        for (int c = 0; c < NC; ++c) {
            CP_WAIT1();
            __syncthreads();

            if (c + 2 < NC) {
                int ns = stage + 2; if (ns >= NSTAGE) ns -= NSTAGE;
                ISSUE_STAGE(ns, (c + 2) * 64);
            }

            const uint32_t sA = sb + (uint32_t)stage * STGH;
            const uint32_t sB = sA + ASZH;

            uint32_t af[2][4][4], bf[2][2][4];
#pragma unroll
            for (int mt = 0; mt < 4; ++mt)
                ldsm4(af[0][mt], sA + swz(laRow + mt * 16, laKg));
            ldsm4(bf[0][0], sB + swz(lbRow,      lbKg));
            ldsm4(bf[0][1], sB + swz(lbRow + 16, lbKg));

#pragma unroll
            for (int ks = 0; ks < 4; ++ks) {
                const int cur = ks & 1;
                if (ks < 3) {
                    const int kg = 2 * (ks + 1);
#pragma unroll
                    for (int mt = 0; mt < 4; ++mt)
                        ldsm4(af[cur ^ 1][mt],
                              sA + swz(laRow + mt * 16, kg + laKg));
                    ldsm4(bf[cur ^ 1][0], sB + swz(lbRow,      kg + lbKg));
                    ldsm4(bf[cur ^ 1][1], sB + swz(lbRow + 16, kg + lbKg));
                }
#pragma unroll
                for (int mt = 0; mt < 4; ++mt)
#pragma unroll
                    for (int nt = 0; nt < 4; ++nt)
                        mma_f16(acc[mt][nt], af[cur][mt],
                                &bf[cur][nt >> 1][(nt & 1) * 2]);
            }

            if (++stage >= NSTAGE) stage = 0;
        }
        CP_WAIT0();

        // epilogue
#pragma unroll
        for (int mt = 0; mt < 4; ++mt) {
#pragma unroll
            for (int nt = 0; nt < 4; ++nt) {
                int row = bm + warpM + mt * 16 + (lane >> 2);
                int col = bn + warpN + nt * 8 + (lane & 3) * 2;
                if (HALF_OUT) {
                    __half* C = (__half*)Cv;
                    __half2 h0 = __floats2half2_rn(acc[mt][nt][0], acc[mt][nt][1]);
                    __half2 h1 = __floats2half2_rn(acc[mt][nt][2], acc[mt][nt][3]);
                    *reinterpret_cast<__half2*>(C + (size_t)row * N + col) = h0;
                    *reinterpret_cast<__half2*>(C + (size_t)(row + 8) * N + col) = h1;
                } else {
                    float* C = (float*)Cv;
                    float2 v0 = make_float2(acc[mt][nt][0], acc[mt][nt][1]);
                    float2 v1 = make_float2(acc[mt][nt][2], acc[mt][nt][3]);
                    *reinterpret_cast<float2*>(C + (size_t)row * N + col) = v0;
                    *reinterpret_cast<float2*>(C + (size_t)(row + 8) * N + col) = v1;
                }
            }
        }
        __syncthreads();   // tile transition
    }
#undef ISSUE_STAGE
}

// ---------------------------------------------------------------------------
// Kernel 0: fused prologue.
// Block 0: coefficients. Blocks 1..768: weights -> fp16. Rest: x -> fp16.
// ---------------------------------------------------------------------------
#define WBLK (KV * HIDDEN / 256)            // 768
#define XBLK (MTOT * HIDDEN / 1024)         // 12288

__global__ void pre_kernel(const float* __restrict__ x,
                           const float* __restrict__ Wv,
                           const float* __restrict__ Wo) {
    const int b = blockIdx.x;
    if (b == 0) {
        __shared__ float warp_sum[8];
        const int t = threadIdx.x;
        const int lane = t & 31, warp = t >> 5;
        const float cc = -logf(10000.0f) / 384.0f;
        for (int d = 0; d <= DMAX; ++d) {
            float val = 0.f;
            for (int j = t; j < 384; j += 256)
                val += cosf((float)d * __expf(cc * (float)j));
#pragma unroll
            for (int o = 16; o; o >>= 1)
                val += __shfl_xor_sync(0xffffffffu, val, o);
            if (lane == 0) warp_sum[warp] = val;
            __syncthreads();
            if (t == 0) {
                float w = 0.f;
#pragma unroll
                for (int i = 0; i < 8; ++i) w += warp_sum[i];
                g_e[d] = expf(w - 384.0f);
            }
            __syncthreads();
        }
    } else if (b <= WBLK) {
        int i = (b - 1) * 256 + threadIdx.x;
        g_wvh[i] = __float2half_rn(Wv[i]);
        g_woh[i] = __float2half_rn(Wo[i]);
    } else {
        int i = (b - 1 - WBLK) * 1024 + threadIdx.x * 4;
        float4 v = *reinterpret_cast<const float4*>(x + i);
        __half2 h0 = __floats2half2_rn(v.x, v.y);
        __half2 h1 = __floats2half2_rn(v.z, v.w);
        uint2 o;
        o.x = *reinterpret_cast<uint32_t*>(&h0);
        o.y = *reinterpret_cast<uint32_t*>(&h1);
        *reinterpret_cast<uint2*>(g_xh + i) = o;
    }
}

// ---------------------------------------------------------------------------
// Kernel 2: softmax == normalized 15-tap convolution along seq (all fp16 IO).
// Sliding window: 4 consecutive rows x 8 cols per thread; fp32 accumulate.
// ---------------------------------------------------------------------------
__global__ __launch_bounds__(256) void smooth_kernel() {
    const int NCG = KV / 8;                       // 32 col-groups of 8
    int idx = blockIdx.x * blockDim.x + threadIdx.x;
    if (idx >= (MTOT / 4) * NCG) return;
    const int mg = idx >> 5;                      // 4-row group
    const int c8 = (idx & 31) * 8;                // col base
    const int m0 = mg << 2;
    const int s0 = m0 & (SEQ - 1);

    float earr[15];
#pragma unroll
    for (int t = 0; t < 15; ++t) earr[t] = g_e[t < 7 ? 7 - t : t - 7];

    // window: 18 rows x 8 fp16 (uint2 = 4 half2)
    uint2 w[18];
#pragma unroll
    for (int j = 0; j < 18; ++j) {
        int s = s0 - 7 + j;
        if (s >= 0 && s < SEQ)
            w[j] = *reinterpret_cast<const uint2*>(
                g_vh + (size_t)(m0 - 7 + j) * KV + c8);
        else
            w[j] = make_uint2(0u, 0u);
    }

#pragma unroll
    for (int i = 0; i < 4; ++i) {
        const int s = s0 + i;
        float acc[8];
#pragma unroll
        for (int q = 0; q < 8; ++q) acc[q] = 0.f;
#pragma unroll
        for (int t = 0; t < 15; ++t) {
            const float e = earr[t];
            const uint2 u = w[i + t];
            float2 p0 = __half22float2(*reinterpret_cast<const __half2*>(&u.x));
            float2 p1 = __half22float2(
                *reinterpret_cast<const __half2*>(((const uint32_t*)&u) + 1));
            // unpack all four half2 lanes
            __half2 h0, h1, h2, h3;
            *reinterpret_cast<uint32_t*>(&h0) = u.x;
            *reinterpret_cast<uint32_t*>(&h1) = u.x;   // placeholder (unused)
            (void)p0; (void)p1; (void)h1; (void)h2; (void)h3; (void)h0;
            const uint32_t* uw = reinterpret_cast<const uint32_t*>(&u);
#pragma unroll
            for (int p = 0; p < 2; ++p) {
                __half2 hh;
                *reinterpret_cast<uint32_t*>(&hh) = uw[p];
                float2 f = __half22float2(hh);
                acc[p * 2 + 0] += e * f.x;
                acc[p * 2 + 1] += e * f.y;
            }
        }
        // second 4 cols come from the same uint2? No: uint2 = 8 bytes = 4 halves.
        // Handle cols 4..7 via a second window pass is wrong; instead the
        // window uint2 only covers 4 halves. Use a second uint2 window.
        float z = 1.0f;
#pragma unroll
        for (int d = 1; d <= DMAX; ++d) {
            if (s >= d)       z += g_e[d];
            if (s + d < SEQ)  z += g_e[d];
        }
        const float inv = 1.0f / z;
        __half2 o0 = __floats2half2_rn(acc[0] * inv, acc[1] * inv);
        __half2 o1 = __floats2half2_rn(acc[2] * inv, acc[3] * inv);
        uint2 o;
        o.x = *reinterpret_cast<uint32_t*>(&o0);
        o.y = *reinterpret_cast<uint32_t*>(&o1);
        *reinterpret_cast<uint2*>(g_ah + (size_t)(m0 + i) * KV + c8) = o;
        // cols 4..7 handled below
        (void)acc;
    }

    // second half of the 8-col group (cols c8+4..c8+7)
    uint2 w2[18];
#pragma unroll
    for (int j = 0; j < 18; ++j) {
        int s = s0 - 7 + j;
        if (s >= 0 && s < SEQ)
            w2[j] = *reinterpret_cast<const uint2*>(
                g_vh + (size_t)(m0 - 7 + j) * KV + c8 + 4);
        else
            w2[j] = make_uint2(0u, 0u);
    }
#pragma unroll
    for (int i = 0; i < 4; ++i) {
        const int s = s0 + i;
        float acc[4] = {0.f, 0.f, 0.f, 0.f};
#pragma unroll
        for (int t = 0; t < 15; ++t) {
            const float e = earr[t];
            const uint32_t* uw = reinterpret_cast<const uint32_t*>(&w2[i + t]);
#pragma unroll
            for (int p = 0; p < 2; ++p) {
                __half2 hh;
                *reinterpret_cast<uint32_t*>(&hh) = uw[p];
                float2 f = __half22float2(hh);
                acc[p * 2 + 0] += e * f.x;
                acc[p * 2 + 1] += e * f.y;
            }
        }
        float z = 1.0f;
#pragma unroll
        for (int d = 1; d <= DMAX; ++d) {
            if (s >= d)       z += g_e[d];
            if (s + d < SEQ)  z += g_e[d];
        }
        const float inv = 1.0f / z;
        __half2 o0 = __floats2half2_rn(acc[0] * inv, acc[1] * inv);
        __half2 o1 = __floats2half2_rn(acc[2] * inv, acc[3] * inv);
        uint2 o;
        o.x = *reinterpret_cast<uint32_t*>(&o0);
        o.y = *reinterpret_cast<uint32_t*>(&o1);
        *reinterpret_cast<uint2*>(g_ah + (size_t)(m0 + i) * KV + c8 + 4) = o;
    }
}

// ---------------------------------------------------------------------------
// Launch
// ---------------------------------------------------------------------------
extern "C" void kernel_launch(void* const* d_in, const int* in_sizes, int n_in,
                              void* d_out, int out_size) {
    const float* x  = (const float*)d_in[0];
    // d_in[1] = Wq, d_in[2] = Wk are dead (rope ignores its input)
    const float* Wv = (const float*)d_in[3];
    const float* Wo = (const float*)d_in[4];
    float* out = (float*)d_out;

    __half* vh_buf; cudaGetSymbolAddress((void**)&vh_buf, g_vh);
    __half* ah_buf; cudaGetSymbolAddress((void**)&ah_buf, g_ah);
    __half* xh_buf; cudaGetSymbolAddress((void**)&xh_buf, g_xh);
    __half* wv_buf; cudaGetSymbolAddress((void**)&wv_buf, g_wvh);
    __half* wo_buf; cudaGetSymbolAddress((void**)&wo_buf, g_woh);

    const int SMEM_BYTES = NSTAGE * STGH + 128;   // ~144 KB
    cudaFuncSetAttribute(gemm_fp16<true>,
                         cudaFuncAttributeMaxDynamicSharedMemorySize, SMEM_BYTES);
    cudaFuncSetAttribute(gemm_fp16<false>,
                         cudaFuncAttributeMaxDynamicSharedMemorySize, SMEM_BYTES);

    // 0) coefficients + fp16 pre-conversion of Wv, Wo, x (one launch)
    pre_kernel<<<1 + WBLK + XBLK, 256>>>(x, Wv, Wo);

    // 1) v = x @ Wv^T -> fp16  (tiles = 128, K=768 -> NC=12)
    gemm_fp16<true><<<128, 512, SMEM_BYTES>>>(xh_buf, wv_buf, vh_buf,
                                              MTOT, KV, HIDDEN);

    // 2) softmax(attn) @ v == normalized 15-tap convolution (fp16 -> fp16)
    {
        int n = (MTOT / 4) * (KV / 8);
        smooth_kernel<<<(n + 255) / 256, 256>>>();
    }

    // 3) out = a @ Wo^T -> fp32 (tiles = 384, persistent, K=256 -> NC=4)
    gemm_fp16<false><<<NSM, 512, SMEM_BYTES>>>(ah_buf, wo_buf, out,
                                               MTOT, HIDDEN, KV);
}